// round 1
// baseline (speedup 1.0000x reference)
#include <cuda_runtime.h>
#include <cuda_bf16.h>
#include <cuda_fp16.h>

#define NB   2
#define NC   128
#define NH   64
#define NW   512
#define NHW  32768
#define EPSF 1e-5f

// ---------------- scratch (device globals; no allocations allowed) ----------
__device__ float4 g_T[NB * 32 * NHW];   // relu(bn(fw@feat)), layout [b][og][p][4]
__device__ float4 g_Q[NB * 32 * NHW];   // pscale*(pw@cart),  layout [b][og][p][4]
__device__ float  g_fwT[NC * NC];       // fwT[c][o] = fw[o][c]*fscale[o]
__device__ float  g_fshift[NC];
__device__ float  g_pws[NC * 3];        // pscale[o]*pw[o][j]
__device__ float  g_pshift[NC];
__device__ float  g_escale[4];
__device__ float  g_eshift[4];
__device__ float  g_maskF[NB * NHW];
__device__ int    g_maskMode;

// ---------------- mask dtype detection --------------------------------------
__global__ void detect_mask_kernel(const unsigned int* __restrict__ m) {
    __shared__ unsigned int fl;
    int t = threadIdx.x;
    if (t == 0) fl = 0;
    __syncthreads();
    unsigned int flags = 0;
    for (int k = t; k < 1024; k += 256) {   // 4KB scan: safe for u8 (64KB buffer)
        unsigned int x = m[k];
        if (x == 0u) continue;
        unsigned int lo = x & 0xFFFFu, hi = x >> 16;
        if (x == 0x3F800000u) flags |= 1u;                           // f32 1.0 (ambig w/ bf16 pair)
        bool blo = (lo == 0u || lo == 0x3F80u), bhi = (hi == 0u || hi == 0x3F80u);
        bool hlo = (lo == 0u || lo == 0x3C00u), hhi = (hi == 0u || hi == 0x3C00u);
        if (blo && bhi && x != 0x3F800000u) flags |= 8u;             // bf16 definite
        else if (hlo && hhi) flags |= 16u;                            // f16 definite
        else if ((x & 0xFEFEFEFEu) == 0u) {                           // bytes in {0,1}
            if (x & 0xFFFFFF00u) flags |= 2u;                         // u8
            else flags |= 4u;                                         // i32 (x==1)
        }
    }
    atomicOr(&fl, flags);
    __syncthreads();
    if (t == 0) {
        unsigned int f = fl;
        int mode = 0;                      // default f32
        if (f & 8u)       mode = 3;       // bf16
        else if (f & 1u)  mode = 0;       // f32
        else if (f & 16u) mode = 4;       // f16
        else if (f & 2u)  mode = 1;       // u8
        else if (f & 4u)  mode = 2;       // i32
        g_maskMode = mode;
    }
}

__global__ void convert_mask_kernel(const void* __restrict__ m) {
    int i = blockIdx.x * blockDim.x + threadIdx.x;
    if (i >= NB * NHW) return;
    int mode = g_maskMode;
    float v;
    if (mode == 0)      v = ((const float*)m)[i];
    else if (mode == 1) v = (float)((const unsigned char*)m)[i];
    else if (mode == 2) v = (float)((const int*)m)[i];
    else if (mode == 3) v = __bfloat162float(((const __nv_bfloat16*)m)[i]);
    else                v = __half2float(((const __half*)m)[i]);
    g_maskF[i] = (v != 0.0f) ? 1.0f : 0.0f;
}

// ---------------- param prep (BN folding, fw transpose) ---------------------
__global__ void prep_kernel(const float* __restrict__ fw, const float* __restrict__ fg,
                            const float* __restrict__ fb_, const float* __restrict__ fm,
                            const float* __restrict__ fv, const float* __restrict__ pw,
                            const float* __restrict__ pg, const float* __restrict__ pb_,
                            const float* __restrict__ pm, const float* __restrict__ pv,
                            const float* __restrict__ eg, const float* __restrict__ eb_,
                            const float* __restrict__ em, const float* __restrict__ ev) {
    int idx = blockIdx.x * blockDim.x + threadIdx.x;
    if (idx < NC * NC) {
        int o = idx & (NC - 1), c = idx >> 7;
        float fs = fg[o] * rsqrtf(fv[o] + EPSF);
        g_fwT[c * NC + o] = fw[o * NC + c] * fs;
    }
    if (idx < NC) {
        int o = idx;
        float fs = fg[o] * rsqrtf(fv[o] + EPSF);
        g_fshift[o] = fb_[o] - fm[o] * fs;
        float ps = pg[o] * rsqrtf(pv[o] + EPSF);
        g_pshift[o] = pb_[o] - pm[o] * ps;
        g_pws[o * 3 + 0] = pw[o * 3 + 0] * ps;
        g_pws[o * 3 + 1] = pw[o * 3 + 1] * ps;
        g_pws[o * 3 + 2] = pw[o * 3 + 2] * ps;
    }
    if (idx < 3) {
        float es = eg[idx] * rsqrtf(ev[idx] + EPSF);
        g_escale[idx] = es;
        g_eshift[idx] = eb_[idx] - em[idx] * es;
    }
}

// ---------------- pass 1: GEMM (T = relu(bn(fw@feat))) + Qs -----------------
__global__ void __launch_bounds__(256)
gemm_kernel(const float* __restrict__ feat, const float* __restrict__ cart) {
    __shared__ float As[16][128];   // As[k][o] (fw^T, pre-scaled)
    __shared__ float Bs[16][128];   // Bs[k][p]
    const int b = blockIdx.y;
    const int ptile = blockIdx.x * 128;
    const int tid = threadIdx.x;
    const int ty = tid >> 4, tx = tid & 15;
    const int o0 = ty * 8;

    const float* fb = feat + (size_t)b * NC * NHW + ptile;

    float acc[8][8];
#pragma unroll
    for (int j = 0; j < 8; j++)
#pragma unroll
        for (int i = 0; i < 8; i++) acc[j][i] = 0.0f;

    for (int kk = 0; kk < NC; kk += 16) {
#pragma unroll
        for (int i = 0; i < 8; i++) {
            int idx = tid + i * 256;
            int k = idx >> 7, x = idx & 127;
            As[k][x] = g_fwT[(kk + k) * NC + x];
            Bs[k][x] = fb[(size_t)(kk + k) * NHW + x];
        }
        __syncthreads();
#pragma unroll
        for (int k = 0; k < 16; k++) {
            float a[8], bv[8];
            *(float4*)&a[0] = *(const float4*)&As[k][o0];
            *(float4*)&a[4] = *(const float4*)&As[k][o0 + 4];
#pragma unroll
            for (int i = 0; i < 8; i++) bv[i] = Bs[k][tx + 16 * i];
#pragma unroll
            for (int j = 0; j < 8; j++)
#pragma unroll
                for (int i = 0; i < 8; i++) acc[j][i] = fmaf(a[j], bv[i], acc[j][i]);
        }
        __syncthreads();
    }

    // epilogue: T = relu(acc + fshift); Qs = pws @ cart
    float fsh[8], w0[8], w1[8], w2[8];
#pragma unroll
    for (int j = 0; j < 8; j++) {
        fsh[j] = g_fshift[o0 + j];
        w0[j] = g_pws[(o0 + j) * 3 + 0];
        w1[j] = g_pws[(o0 + j) * 3 + 1];
        w2[j] = g_pws[(o0 + j) * 3 + 2];
    }
    const int og0 = o0 >> 2;           // two consecutive channel-groups
    const size_t base0 = ((size_t)b * 32 + og0) * NHW;
    const size_t base1 = ((size_t)b * 32 + og0 + 1) * NHW;
    const float* cb = cart + (size_t)b * 3 * NHW;

#pragma unroll
    for (int i = 0; i < 8; i++) {
        int p = ptile + tx + 16 * i;
        float4 t0, t1;
        t0.x = fmaxf(acc[0][i] + fsh[0], 0.f);
        t0.y = fmaxf(acc[1][i] + fsh[1], 0.f);
        t0.z = fmaxf(acc[2][i] + fsh[2], 0.f);
        t0.w = fmaxf(acc[3][i] + fsh[3], 0.f);
        t1.x = fmaxf(acc[4][i] + fsh[4], 0.f);
        t1.y = fmaxf(acc[5][i] + fsh[5], 0.f);
        t1.z = fmaxf(acc[6][i] + fsh[6], 0.f);
        t1.w = fmaxf(acc[7][i] + fsh[7], 0.f);
        g_T[base0 + p] = t0;
        g_T[base1 + p] = t1;

        float c0 = cb[p], c1 = cb[NHW + p], c2 = cb[2 * NHW + p];
        float4 q0, q1;
        q0.x = w0[0] * c0 + w1[0] * c1 + w2[0] * c2;
        q0.y = w0[1] * c0 + w1[1] * c1 + w2[1] * c2;
        q0.z = w0[2] * c0 + w1[2] * c1 + w2[2] * c2;
        q0.w = w0[3] * c0 + w1[3] * c1 + w2[3] * c2;
        q1.x = w0[4] * c0 + w1[4] * c1 + w2[4] * c2;
        q1.y = w0[5] * c0 + w1[5] * c1 + w2[5] * c2;
        q1.z = w0[6] * c0 + w1[6] * c1 + w2[6] * c2;
        q1.w = w0[7] * c0 + w1[7] * c1 + w2[7] * c2;
        g_Q[base0 + p] = q0;
        g_Q[base1 + p] = q1;
    }
}

// ---------------- pass 2: masked 3x3 max + e2c residual ---------------------
__global__ void __launch_bounds__(1024)
neigh_kernel(const float* __restrict__ cart, const float* __restrict__ ew,
             float* __restrict__ out) {
    __shared__ float red[3][32][32];   // [j][og][lane]
    const int b = blockIdx.z, h = blockIdx.y;
    const int lane = threadIdx.x & 31, og = threadIdx.x >> 5;
    const int w = blockIdx.x * 32 + lane;
    const int p = h * NW + w;
    const size_t tb = ((size_t)b * 32 + og) * NHW;
    const float* mF = g_maskF + (size_t)b * NHW;

    const float4 ps4 = *(const float4*)&g_pshift[og * 4];
    const float4 qc = g_Q[tb + p];
    const float bx = ps4.x - qc.x, by = ps4.y - qc.y, bz = ps4.z - qc.z, bw = ps4.w - qc.w;

    float gx = 0.f, gy = 0.f, gz = 0.f, gw = 0.f;
#pragma unroll
    for (int dh = -1; dh <= 1; dh++) {
        int hh = h + dh;
        if ((unsigned)hh < NH) {
            int rb = hh * NW;
#pragma unroll
            for (int dw = -1; dw <= 1; dw++) {
                int ww = w + dw;
                if ((unsigned)ww < NW) {
                    int pn = rb + ww;
                    float mu = mF[pn];
                    if (mu != 0.f) {
                        float4 t = g_T[tb + pn];
                        float4 q = g_Q[tb + pn];
                        gx = fmaxf(gx, t.x + fmaxf(q.x + bx, 0.f));
                        gy = fmaxf(gy, t.y + fmaxf(q.y + by, 0.f));
                        gz = fmaxf(gz, t.z + fmaxf(q.z + bz, 0.f));
                        gw = fmaxf(gw, t.w + fmaxf(q.w + bw, 0.f));
                    }
                }
            }
        }
    }

    // geo output: (B,128,H,W) channel-major
    const int o = og * 4;
    out[((size_t)b * NC + o + 0) * NHW + p] = gx;
    out[((size_t)b * NC + o + 1) * NHW + p] = gy;
    out[((size_t)b * NC + o + 2) * NHW + p] = gz;
    out[((size_t)b * NC + o + 3) * NHW + p] = gw;

    // e2c partial dot products
    red[0][og][lane] = ew[0 * NC + o] * gx + ew[0 * NC + o + 1] * gy +
                       ew[0 * NC + o + 2] * gz + ew[0 * NC + o + 3] * gw;
    red[1][og][lane] = ew[1 * NC + o] * gx + ew[1 * NC + o + 1] * gy +
                       ew[1 * NC + o + 2] * gz + ew[1 * NC + o + 3] * gw;
    red[2][og][lane] = ew[2 * NC + o] * gx + ew[2 * NC + o + 1] * gy +
                       ew[2 * NC + o + 2] * gz + ew[2 * NC + o + 3] * gw;
    __syncthreads();

    if (og < 3) {
        const int j = og;
        float s = 0.f;
#pragma unroll
        for (int u = 0; u < 32; u++) s += red[j][u][lane];
        float e2c = g_escale[j] * s + g_eshift[j];
        float m = mF[p];
        float cv = cart[((size_t)b * 3 + j) * NHW + p];
        out[(size_t)NB * NC * NHW + ((size_t)b * 3 + j) * NHW + p] = cv + e2c * m;
    }
}

// ---------------- launch -----------------------------------------------------
extern "C" void kernel_launch(void* const* d_in, const int* in_sizes, int n_in,
                              void* d_out, int out_size) {
    const float* feat = (const float*)d_in[0];
    const float* cart = (const float*)d_in[1];
    const void*  mask = d_in[2];
    const float* pw = (const float*)d_in[3];
    const float* pg = (const float*)d_in[4];
    const float* pb = (const float*)d_in[5];
    const float* pm = (const float*)d_in[6];
    const float* pv = (const float*)d_in[7];
    const float* fw = (const float*)d_in[8];
    const float* fg = (const float*)d_in[9];
    const float* fbp = (const float*)d_in[10];
    const float* fm = (const float*)d_in[11];
    const float* fv = (const float*)d_in[12];
    const float* ew = (const float*)d_in[13];
    const float* eg = (const float*)d_in[14];
    const float* eb = (const float*)d_in[15];
    const float* em = (const float*)d_in[16];
    const float* ev = (const float*)d_in[17];

    detect_mask_kernel<<<1, 256>>>((const unsigned int*)mask);
    convert_mask_kernel<<<(NB * NHW + 255) / 256, 256>>>(mask);
    prep_kernel<<<64, 256>>>(fw, fg, fbp, fm, fv, pw, pg, pb, pm, pv, eg, eb, em, ev);

    dim3 g1(NHW / 128, NB);
    gemm_kernel<<<g1, 256>>>(feat, cart);

    dim3 g2(NW / 32, NH, NB);
    neigh_kernel<<<g2, 1024>>>(cart, ew, (float*)d_out);
}

// round 2
// speedup vs baseline: 1.0507x; 1.0507x over previous
#include <cuda_runtime.h>
#include <cuda_bf16.h>
#include <cuda_fp16.h>

#define NB   2
#define NC   128
#define NH   64
#define NW   512
#define NHW  32768
#define EPSF 1e-5f
#define NEGF (-1.0e30f)

// ---------------- scratch (device globals) ----------------------------------
__device__ float4 g_arrA[NB * 32 * NHW];  // maskfold(T+Q+pshift)  [b][og][p]
__device__ float4 g_arrB[NB * 32 * NHW];  // maskfold(T)           [b][og][p]
__device__ float4 g_arrQ[NB * 32 * NHW];  // Q (unmasked)          [b][og][p]
__device__ float  g_Whi[NC * NC];         // tf32-hi of fw*fscale, [o][c]
__device__ float  g_Wlo[NC * NC];         // tf32-lo
__device__ float  g_fshift[NC];
__device__ float  g_pws[NC * 3];
__device__ float  g_pshift[NC];
__device__ float  g_escale[4];
__device__ float  g_eshift[4];
__device__ float  g_maskF[NB * NHW];
__device__ int    g_maskMode;

__device__ __forceinline__ float to_tf32(float x) {
    float r;
    asm("cvt.rna.tf32.f32 %0, %1;" : "=f"(r) : "f"(x));
    return r;
}

// ---------------- mask dtype detection --------------------------------------
__global__ void detect_mask_kernel(const unsigned int* __restrict__ m) {
    __shared__ unsigned int fl;
    int t = threadIdx.x;
    if (t == 0) fl = 0;
    __syncthreads();
    unsigned int flags = 0;
    for (int k = t; k < 1024; k += 256) {
        unsigned int x = m[k];
        if (x == 0u) continue;
        unsigned int lo = x & 0xFFFFu, hi = x >> 16;
        if (x == 0x3F800000u) flags |= 1u;
        bool blo = (lo == 0u || lo == 0x3F80u), bhi = (hi == 0u || hi == 0x3F80u);
        bool hlo = (lo == 0u || lo == 0x3C00u), hhi = (hi == 0u || hi == 0x3C00u);
        if (blo && bhi && x != 0x3F800000u) flags |= 8u;
        else if (hlo && hhi) flags |= 16u;
        else if ((x & 0xFEFEFEFEu) == 0u) {
            if (x & 0xFFFFFF00u) flags |= 2u;
            else flags |= 4u;
        }
    }
    atomicOr(&fl, flags);
    __syncthreads();
    if (t == 0) {
        unsigned int f = fl;
        int mode = 0;
        if (f & 8u)       mode = 3;
        else if (f & 1u)  mode = 0;
        else if (f & 16u) mode = 4;
        else if (f & 2u)  mode = 1;
        else if (f & 4u)  mode = 2;
        g_maskMode = mode;
    }
}

__global__ void convert_mask_kernel(const void* __restrict__ m) {
    int i = blockIdx.x * blockDim.x + threadIdx.x;
    if (i >= NB * NHW) return;
    int mode = g_maskMode;
    float v;
    if (mode == 0)      v = ((const float*)m)[i];
    else if (mode == 1) v = (float)((const unsigned char*)m)[i];
    else if (mode == 2) v = (float)((const int*)m)[i];
    else if (mode == 3) v = __bfloat162float(((const __nv_bfloat16*)m)[i]);
    else                v = __half2float(((const __half*)m)[i]);
    g_maskF[i] = (v != 0.0f) ? 1.0f : 0.0f;
}

// ---------------- param prep -------------------------------------------------
__global__ void prep_kernel(const float* __restrict__ fw, const float* __restrict__ fg,
                            const float* __restrict__ fb_, const float* __restrict__ fm,
                            const float* __restrict__ fv, const float* __restrict__ pw,
                            const float* __restrict__ pg, const float* __restrict__ pb_,
                            const float* __restrict__ pm, const float* __restrict__ pv,
                            const float* __restrict__ eg, const float* __restrict__ eb_,
                            const float* __restrict__ em, const float* __restrict__ ev) {
    int idx = blockIdx.x * blockDim.x + threadIdx.x;
    if (idx < NC * NC) {
        int o = idx >> 7, c = idx & (NC - 1);
        float fs = fg[o] * rsqrtf(fv[o] + EPSF);
        float v = fw[o * NC + c] * fs;
        float hi = to_tf32(v);
        g_Whi[o * NC + c] = hi;
        g_Wlo[o * NC + c] = to_tf32(v - hi);
    }
    if (idx < NC) {
        int o = idx;
        float fs = fg[o] * rsqrtf(fv[o] + EPSF);
        g_fshift[o] = fb_[o] - fm[o] * fs;
        float ps = pg[o] * rsqrtf(pv[o] + EPSF);
        g_pshift[o] = pb_[o] - pm[o] * ps;
        g_pws[o * 3 + 0] = pw[o * 3 + 0] * ps;
        g_pws[o * 3 + 1] = pw[o * 3 + 1] * ps;
        g_pws[o * 3 + 2] = pw[o * 3 + 2] * ps;
    }
    if (idx < 3) {
        float es = eg[idx] * rsqrtf(ev[idx] + EPSF);
        g_escale[idx] = es;
        g_eshift[idx] = eb_[idx] - em[idx] * es;
    }
}

// ---------------- pass 1: tf32 tensor-core GEMM + epilogue -------------------
// D[o][p] = sum_k W'[o][k] * feat[k][p], 3-term tf32 split.
// Block: 256 thr (8 warps), tile 128(o) x 128(p), K chunked by 16.

#define APITCH 20
#define BPITCH 136
#define SPITCH 66

__device__ __forceinline__ void mma_tf32(float* d, const unsigned* a, const unsigned* b) {
    asm volatile(
        "mma.sync.aligned.m16n8k8.row.col.f32.tf32.tf32.f32 "
        "{%0,%1,%2,%3}, {%4,%5,%6,%7}, {%8,%9}, {%0,%1,%2,%3};"
        : "+f"(d[0]), "+f"(d[1]), "+f"(d[2]), "+f"(d[3])
        : "r"(a[0]), "r"(a[1]), "r"(a[2]), "r"(a[3]), "r"(b[0]), "r"(b[1]));
}

__global__ void __launch_bounds__(256)
gemm_kernel(const float* __restrict__ feat, const float* __restrict__ cart) {
    __shared__ float sm[9472];   // reused: frag buffers, then epilogue transpose
    float* sAh = sm;             // [128][20]
    float* sAl = sm + 2560;      // [128][20]
    float* sBh = sm + 5120;      // [16][136]
    float* sBl = sm + 7296;      // [16][136]

    const int b = blockIdx.y;
    const int ptile = blockIdx.x * 128;
    const int tid = threadIdx.x;
    const int lane = tid & 31, wid = tid >> 5;
    const int g = lane >> 2, tg = lane & 3;
    const int wm = wid & 1, wn = wid >> 1;

    float acc[4][4][4];
#pragma unroll
    for (int mt = 0; mt < 4; mt++)
#pragma unroll
        for (int nt = 0; nt < 4; nt++)
#pragma unroll
            for (int i = 0; i < 4; i++) acc[mt][nt][i] = 0.0f;

    const float* featB = feat + (size_t)b * NC * NHW + ptile;

    for (int kc = 0; kc < 8; kc++) {
        // stage A chunk (128 x 16, hi+lo)
#pragma unroll
        for (int i = 0; i < 2; i++) {
            int idx4 = tid + i * 256;
            int m = idx4 >> 2, k4 = idx4 & 3;
            float4 h4 = *(const float4*)&g_Whi[m * NC + kc * 16 + k4 * 4];
            float4 l4 = *(const float4*)&g_Wlo[m * NC + kc * 16 + k4 * 4];
            *(float4*)&sAh[m * APITCH + k4 * 4] = h4;
            *(float4*)&sAl[m * APITCH + k4 * 4] = l4;
        }
        // stage B chunk (16 x 128), convert f32 -> tf32 hi/lo
#pragma unroll
        for (int i = 0; i < 2; i++) {
            int idx4 = tid + i * 256;
            int k = idx4 >> 5, p4 = idx4 & 31;
            float4 x = *(const float4*)&featB[(size_t)(kc * 16 + k) * NHW + p4 * 4];
            float4 h4, l4;
            h4.x = to_tf32(x.x); l4.x = to_tf32(x.x - h4.x);
            h4.y = to_tf32(x.y); l4.y = to_tf32(x.y - h4.y);
            h4.z = to_tf32(x.z); l4.z = to_tf32(x.z - h4.z);
            h4.w = to_tf32(x.w); l4.w = to_tf32(x.w - h4.w);
            *(float4*)&sBh[k * BPITCH + p4 * 4] = h4;
            *(float4*)&sBl[k * BPITCH + p4 * 4] = l4;
        }
        __syncthreads();

#pragma unroll
        for (int ks = 0; ks < 2; ks++) {
            const int k0 = ks * 8;
            unsigned ah[4][4], al[4][4], bh[4][2], bl[4][2];
#pragma unroll
            for (int mt = 0; mt < 4; mt++) {
                int r = wm * 64 + mt * 16 + g;
                ah[mt][0] = __float_as_uint(sAh[r * APITCH + k0 + tg]);
                ah[mt][1] = __float_as_uint(sAh[(r + 8) * APITCH + k0 + tg]);
                ah[mt][2] = __float_as_uint(sAh[r * APITCH + k0 + tg + 4]);
                ah[mt][3] = __float_as_uint(sAh[(r + 8) * APITCH + k0 + tg + 4]);
                al[mt][0] = __float_as_uint(sAl[r * APITCH + k0 + tg]);
                al[mt][1] = __float_as_uint(sAl[(r + 8) * APITCH + k0 + tg]);
                al[mt][2] = __float_as_uint(sAl[r * APITCH + k0 + tg + 4]);
                al[mt][3] = __float_as_uint(sAl[(r + 8) * APITCH + k0 + tg + 4]);
            }
#pragma unroll
            for (int nt = 0; nt < 4; nt++) {
                int ncol = wn * 32 + nt * 8 + g;
                bh[nt][0] = __float_as_uint(sBh[(k0 + tg) * BPITCH + ncol]);
                bh[nt][1] = __float_as_uint(sBh[(k0 + tg + 4) * BPITCH + ncol]);
                bl[nt][0] = __float_as_uint(sBl[(k0 + tg) * BPITCH + ncol]);
                bl[nt][1] = __float_as_uint(sBl[(k0 + tg + 4) * BPITCH + ncol]);
            }
#pragma unroll
            for (int mt = 0; mt < 4; mt++)
#pragma unroll
                for (int nt = 0; nt < 4; nt++) {
                    mma_tf32(acc[mt][nt], ah[mt], bh[nt]);
                    mma_tf32(acc[mt][nt], al[mt], bh[nt]);
                    mma_tf32(acc[mt][nt], ah[mt], bl[nt]);
                }
        }
        __syncthreads();
    }

    // ---- epilogue: transpose via smem, fold BN/relu/mask, write A/B/Q ------
    float* S = sm;   // [128][66] = 33.8KB
    const float* maskB = g_maskF + (size_t)b * NHW;
    const float* cartB = cart + (size_t)b * 3 * NHW;

    for (int hf = 0; hf < 2; hf++) {
        __syncthreads();
        if ((wn >> 1) == hf) {
#pragma unroll
            for (int mt = 0; mt < 4; mt++) {
                int r0 = wm * 64 + mt * 16 + g;
#pragma unroll
                for (int nt = 0; nt < 4; nt++) {
                    int col = (wn & 1) * 32 + nt * 8 + 2 * tg;
                    S[r0 * SPITCH + col]     = acc[mt][nt][0];
                    S[r0 * SPITCH + col + 1] = acc[mt][nt][1];
                    S[(r0 + 8) * SPITCH + col]     = acc[mt][nt][2];
                    S[(r0 + 8) * SPITCH + col + 1] = acc[mt][nt][3];
                }
            }
        }
        __syncthreads();
#pragma unroll
        for (int i = 0; i < 8; i++) {
            int item = tid + i * 256;
            int og = item & 31, px = item >> 5;
            int p = ptile + hf * 64 + px;
            int o = og * 4;
            float t0 = fmaxf(S[(o + 0) * SPITCH + px] + g_fshift[o + 0], 0.f);
            float t1 = fmaxf(S[(o + 1) * SPITCH + px] + g_fshift[o + 1], 0.f);
            float t2 = fmaxf(S[(o + 2) * SPITCH + px] + g_fshift[o + 2], 0.f);
            float t3 = fmaxf(S[(o + 3) * SPITCH + px] + g_fshift[o + 3], 0.f);
            float c0 = cartB[p], c1 = cartB[NHW + p], c2 = cartB[2 * NHW + p];
            float4 q;
            q.x = g_pws[(o + 0) * 3] * c0 + g_pws[(o + 0) * 3 + 1] * c1 + g_pws[(o + 0) * 3 + 2] * c2;
            q.y = g_pws[(o + 1) * 3] * c0 + g_pws[(o + 1) * 3 + 1] * c1 + g_pws[(o + 1) * 3 + 2] * c2;
            q.z = g_pws[(o + 2) * 3] * c0 + g_pws[(o + 2) * 3 + 1] * c1 + g_pws[(o + 2) * 3 + 2] * c2;
            q.w = g_pws[(o + 3) * 3] * c0 + g_pws[(o + 3) * 3 + 1] * c1 + g_pws[(o + 3) * 3 + 2] * c2;
            bool valid = (maskB[p] != 0.0f);
            float4 A4, B4;
            A4.x = valid ? t0 + q.x + g_pshift[o + 0] : NEGF;
            A4.y = valid ? t1 + q.y + g_pshift[o + 1] : NEGF;
            A4.z = valid ? t2 + q.z + g_pshift[o + 2] : NEGF;
            A4.w = valid ? t3 + q.w + g_pshift[o + 3] : NEGF;
            B4.x = valid ? t0 : NEGF;
            B4.y = valid ? t1 : NEGF;
            B4.z = valid ? t2 : NEGF;
            B4.w = valid ? t3 : NEGF;
            size_t base = ((size_t)b * 32 + og) * NHW + p;
            g_arrA[base] = A4;
            g_arrB[base] = B4;
            g_arrQ[base] = q;
        }
    }
}

// ---------------- pass 2: separable masked 3x3 maxpool + geo -----------------
#define HT 16

__device__ __forceinline__ void hrow(int hh, int w,
                                     const float4* __restrict__ pA,
                                     const float4* __restrict__ pB,
                                     float4& ha, float4& hb) {
    const float4 NEG4 = make_float4(NEGF, NEGF, NEGF, NEGF);
    if ((unsigned)hh >= NH) { ha = NEG4; hb = NEG4; return; }
    int idx = hh * NW + w;
    float4 a0 = pA[idx];
    float4 am = (w > 0) ? pA[idx - 1] : NEG4;
    float4 ap = (w < NW - 1) ? pA[idx + 1] : NEG4;
    ha.x = fmaxf(fmaxf(am.x, a0.x), ap.x);
    ha.y = fmaxf(fmaxf(am.y, a0.y), ap.y);
    ha.z = fmaxf(fmaxf(am.z, a0.z), ap.z);
    ha.w = fmaxf(fmaxf(am.w, a0.w), ap.w);
    float4 b0 = pB[idx];
    float4 bm = (w > 0) ? pB[idx - 1] : NEG4;
    float4 bp = (w < NW - 1) ? pB[idx + 1] : NEG4;
    hb.x = fmaxf(fmaxf(bm.x, b0.x), bp.x);
    hb.y = fmaxf(fmaxf(bm.y, b0.y), bp.y);
    hb.z = fmaxf(fmaxf(bm.z, b0.z), bp.z);
    hb.w = fmaxf(fmaxf(bm.w, b0.w), bp.w);
}

__global__ void __launch_bounds__(1024, 1)
pool_kernel(float* __restrict__ out) {
    const int b = blockIdx.z;
    const int h0 = blockIdx.y * HT;
    const int lane = threadIdx.x & 31, og = threadIdx.x >> 5;
    const int w = blockIdx.x * 32 + lane;

    const size_t plane = ((size_t)b * 32 + og) * NHW;
    const float4* pA = g_arrA + plane;
    const float4* pB = g_arrB + plane;
    const float4* pQ = g_arrQ + plane;
    float* outB = out + ((size_t)b * NC + og * 4) * NHW;

    float4 mA, mB, cA, cB, nA, nB;
    hrow(h0 - 1, w, pA, pB, mA, mB);
    hrow(h0,     w, pA, pB, cA, cB);

    for (int r = 0; r < HT; r++) {
        int h = h0 + r;
        hrow(h + 1, w, pA, pB, nA, nB);
        float4 q = pQ[h * NW + w];
        float gx = fmaxf(fmaxf(fmaxf(fmaxf(mA.x, cA.x), nA.x) - q.x,
                               fmaxf(fmaxf(mB.x, cB.x), nB.x)), 0.f);
        float gy = fmaxf(fmaxf(fmaxf(fmaxf(mA.y, cA.y), nA.y) - q.y,
                               fmaxf(fmaxf(mB.y, cB.y), nB.y)), 0.f);
        float gz = fmaxf(fmaxf(fmaxf(fmaxf(mA.z, cA.z), nA.z) - q.z,
                               fmaxf(fmaxf(mB.z, cB.z), nB.z)), 0.f);
        float gw = fmaxf(fmaxf(fmaxf(fmaxf(mA.w, cA.w), nA.w) - q.w,
                               fmaxf(fmaxf(mB.w, cB.w), nB.w)), 0.f);
        int p = h * NW + w;
        outB[p] = gx;
        outB[NHW + p] = gy;
        outB[2 * NHW + p] = gz;
        outB[3 * NHW + p] = gw;
        mA = cA; cA = nA;
        mB = cB; cB = nB;
    }
}

// ---------------- pass 3: e2c residual ---------------------------------------
__global__ void __launch_bounds__(256)
e2c_kernel(const float* __restrict__ cart, const float* __restrict__ ew,
           float* __restrict__ out) {
    int pxg = blockIdx.x * blockDim.x + threadIdx.x;
    if (pxg >= NB * NHW) return;
    int b = pxg >> 15, p = pxg & (NHW - 1);
    const float* geo = out + (size_t)b * NC * NHW + p;
    float s0 = 0.f, s1 = 0.f, s2 = 0.f;
#pragma unroll 8
    for (int c = 0; c < NC; c++) {
        float gv = geo[(size_t)c * NHW];
        s0 += ew[c] * gv;
        s1 += ew[NC + c] * gv;
        s2 += ew[2 * NC + c] * gv;
    }
    float m = g_maskF[pxg];
    size_t ob = (size_t)NB * NC * NHW;
    out[ob + ((size_t)b * 3 + 0) * NHW + p] =
        cart[((size_t)b * 3 + 0) * NHW + p] + (g_escale[0] * s0 + g_eshift[0]) * m;
    out[ob + ((size_t)b * 3 + 1) * NHW + p] =
        cart[((size_t)b * 3 + 1) * NHW + p] + (g_escale[1] * s1 + g_eshift[1]) * m;
    out[ob + ((size_t)b * 3 + 2) * NHW + p] =
        cart[((size_t)b * 3 + 2) * NHW + p] + (g_escale[2] * s2 + g_eshift[2]) * m;
}

// ---------------- launch -----------------------------------------------------
extern "C" void kernel_launch(void* const* d_in, const int* in_sizes, int n_in,
                              void* d_out, int out_size) {
    const float* feat = (const float*)d_in[0];
    const float* cart = (const float*)d_in[1];
    const void*  mask = d_in[2];
    const float* pw = (const float*)d_in[3];
    const float* pg = (const float*)d_in[4];
    const float* pb = (const float*)d_in[5];
    const float* pm = (const float*)d_in[6];
    const float* pv = (const float*)d_in[7];
    const float* fw = (const float*)d_in[8];
    const float* fg = (const float*)d_in[9];
    const float* fbp = (const float*)d_in[10];
    const float* fm = (const float*)d_in[11];
    const float* fv = (const float*)d_in[12];
    const float* ew = (const float*)d_in[13];
    const float* eg = (const float*)d_in[14];
    const float* eb = (const float*)d_in[15];
    const float* em = (const float*)d_in[16];
    const float* ev = (const float*)d_in[17];

    detect_mask_kernel<<<1, 256>>>((const unsigned int*)mask);
    convert_mask_kernel<<<(NB * NHW + 255) / 256, 256>>>(mask);
    prep_kernel<<<64, 256>>>(fw, fg, fbp, fm, fv, pw, pg, pb, pm, pv, eg, eb, em, ev);

    dim3 g1(NHW / 128, NB);
    gemm_kernel<<<g1, 256>>>(feat, cart);

    dim3 g2(NW / 32, NH / HT, NB);
    pool_kernel<<<g2, 1024>>>((float*)d_out);

    e2c_kernel<<<(NB * NHW + 255) / 256, 256>>>(cart, ew, (float*)d_out);
}

// round 3
// speedup vs baseline: 1.2085x; 1.1502x over previous
#include <cuda_runtime.h>
#include <cuda_bf16.h>
#include <cuda_fp16.h>

#define NB   2
#define NC   128
#define NH   64
#define NW   512
#define NHW  32768
#define EPSF 1e-5f
#define NEGF (-1.0e30f)

// ---------------- scratch (device globals) ----------------------------------
__device__ float4 g_arrA[NB * 32 * NHW];  // maskfold(T+Q+pshift)  [b][og][p]
__device__ float4 g_arrB[NB * 32 * NHW];  // maskfold(T)           [b][og][p]
__device__ __align__(16) __half g_Whi16[NC * NC];   // fp16-hi of fw*fscale [o][c]
__device__ __align__(16) __half g_Wlo16[NC * NC];   // fp16-lo
__device__ float  g_fshift[NC];
__device__ float  g_pws[NC * 3];
__device__ float  g_pshift[NC];
__device__ float  g_escale[4];
__device__ float  g_eshift[4];
__device__ float  g_maskF[NB * NHW];
__device__ int    g_maskMode;

// ---------------- mask dtype detection --------------------------------------
__global__ void detect_mask_kernel(const unsigned int* __restrict__ m) {
    __shared__ unsigned int fl;
    int t = threadIdx.x;
    if (t == 0) fl = 0;
    __syncthreads();
    unsigned int flags = 0;
    for (int k = t; k < 1024; k += 256) {
        unsigned int x = m[k];
        if (x == 0u) continue;
        unsigned int lo = x & 0xFFFFu, hi = x >> 16;
        if (x == 0x3F800000u) flags |= 1u;
        bool blo = (lo == 0u || lo == 0x3F80u), bhi = (hi == 0u || hi == 0x3F80u);
        bool hlo = (lo == 0u || lo == 0x3C00u), hhi = (hi == 0u || hi == 0x3C00u);
        if (blo && bhi && x != 0x3F800000u) flags |= 8u;
        else if (hlo && hhi) flags |= 16u;
        else if ((x & 0xFEFEFEFEu) == 0u) {
            if (x & 0xFFFFFF00u) flags |= 2u;
            else flags |= 4u;
        }
    }
    atomicOr(&fl, flags);
    __syncthreads();
    if (t == 0) {
        unsigned int f = fl;
        int mode = 0;
        if (f & 8u)       mode = 3;
        else if (f & 1u)  mode = 0;
        else if (f & 16u) mode = 4;
        else if (f & 2u)  mode = 1;
        else if (f & 4u)  mode = 2;
        g_maskMode = mode;
    }
}

__global__ void convert_mask_kernel(const void* __restrict__ m) {
    int i = blockIdx.x * blockDim.x + threadIdx.x;
    if (i >= NB * NHW) return;
    int mode = g_maskMode;
    float v;
    if (mode == 0)      v = ((const float*)m)[i];
    else if (mode == 1) v = (float)((const unsigned char*)m)[i];
    else if (mode == 2) v = (float)((const int*)m)[i];
    else if (mode == 3) v = __bfloat162float(((const __nv_bfloat16*)m)[i]);
    else                v = __half2float(((const __half*)m)[i]);
    g_maskF[i] = (v != 0.0f) ? 1.0f : 0.0f;
}

// ---------------- param prep -------------------------------------------------
__global__ void prep_kernel(const float* __restrict__ fw, const float* __restrict__ fg,
                            const float* __restrict__ fb_, const float* __restrict__ fm,
                            const float* __restrict__ fv, const float* __restrict__ pw,
                            const float* __restrict__ pg, const float* __restrict__ pb_,
                            const float* __restrict__ pm, const float* __restrict__ pv,
                            const float* __restrict__ eg, const float* __restrict__ eb_,
                            const float* __restrict__ em, const float* __restrict__ ev) {
    int idx = blockIdx.x * blockDim.x + threadIdx.x;
    if (idx < NC * NC) {
        int o = idx >> 7, c = idx & (NC - 1);
        float fs = fg[o] * rsqrtf(fv[o] + EPSF);
        float v = fw[o * NC + c] * fs;
        __half hi = __float2half_rn(v);
        g_Whi16[o * NC + c] = hi;
        g_Wlo16[o * NC + c] = __float2half_rn(v - __half2float(hi));
    }
    if (idx < NC) {
        int o = idx;
        float fs = fg[o] * rsqrtf(fv[o] + EPSF);
        g_fshift[o] = fb_[o] - fm[o] * fs;
        float ps = pg[o] * rsqrtf(pv[o] + EPSF);
        g_pshift[o] = pb_[o] - pm[o] * ps;
        g_pws[o * 3 + 0] = pw[o * 3 + 0] * ps;
        g_pws[o * 3 + 1] = pw[o * 3 + 1] * ps;
        g_pws[o * 3 + 2] = pw[o * 3 + 2] * ps;
    }
    if (idx < 3) {
        float es = eg[idx] * rsqrtf(ev[idx] + EPSF);
        g_escale[idx] = es;
        g_eshift[idx] = eb_[idx] - em[idx] * es;
    }
}

// ---------------- pass 1: fp16 split tensor-core GEMM ------------------------
#define APITCH 24     // halves per A row (16 data + 8 pad)
#define BPITCH 136    // halves per B row (128 data + 8 pad)
#define SPITCH 66

__device__ __forceinline__ unsigned sptr(const void* p) {
    return (unsigned)__cvta_generic_to_shared(p);
}
__device__ __forceinline__ void ldsm4(unsigned& r0, unsigned& r1, unsigned& r2,
                                      unsigned& r3, unsigned a) {
    asm volatile("ldmatrix.sync.aligned.m8n8.x4.shared.b16 {%0,%1,%2,%3}, [%4];"
                 : "=r"(r0), "=r"(r1), "=r"(r2), "=r"(r3) : "r"(a));
}
__device__ __forceinline__ void ldsm4t(unsigned& r0, unsigned& r1, unsigned& r2,
                                       unsigned& r3, unsigned a) {
    asm volatile("ldmatrix.sync.aligned.m8n8.x4.trans.shared.b16 {%0,%1,%2,%3}, [%4];"
                 : "=r"(r0), "=r"(r1), "=r"(r2), "=r"(r3) : "r"(a));
}
__device__ __forceinline__ void mma16816(float* d, const unsigned* a, const unsigned* b) {
    asm volatile(
        "mma.sync.aligned.m16n8k16.row.col.f32.f16.f16.f32 "
        "{%0,%1,%2,%3}, {%4,%5,%6,%7}, {%8,%9}, {%0,%1,%2,%3};"
        : "+f"(d[0]), "+f"(d[1]), "+f"(d[2]), "+f"(d[3])
        : "r"(a[0]), "r"(a[1]), "r"(a[2]), "r"(a[3]), "r"(b[0]), "r"(b[1]));
}

__global__ void __launch_bounds__(256)
gemm_kernel(const float* __restrict__ feat, const float* __restrict__ cart) {
    __shared__ __align__(16) unsigned char smraw[41984];
    __half* sAh = (__half*)smraw;          // [2][128][24]
    __half* sAl = sAh + 6144;              // [2][128][24]
    __half* sBh = sAl + 6144;              // [2][16][136]
    __half* sBl = sBh + 4352;              // [2][16][136]

    const int b = blockIdx.y;
    const int ptile = blockIdx.x * 128;
    const int tid = threadIdx.x;
    const int lane = tid & 31, wid = tid >> 5;
    const int g = lane >> 2, tg = lane & 3;
    const int wm = wid & 1, wn = wid >> 1;

    const float* featB = feat + (size_t)b * NC * NHW + ptile;

    float acc[4][4][4];
#pragma unroll
    for (int mt = 0; mt < 4; mt++)
#pragma unroll
        for (int nt = 0; nt < 4; nt++)
#pragma unroll
            for (int i = 0; i < 4; i++) acc[mt][nt][i] = 0.0f;

    // staging indices
    const int aRow = tid >> 1, aSeg = tid & 1;
    uint4 avh, avl;
    float4 bf0, bf1;

    // ldmatrix lane addressing (precompute half-offsets)
    const int aR = (lane & 7) + ((lane >> 3) & 1) * 8;   // row within m16 tile
    const int aC = (lane >> 4) * 8;                      // k offset
    const int bK = (lane & 7) + ((lane >> 3) & 1) * 8;   // k row
    const int bC = (lane >> 4) * 8;                      // n offset

#define LOAD_CHUNK(kc)                                                              \
    do {                                                                            \
        avh = *(const uint4*)(g_Whi16 + aRow * NC + (kc) * 16 + aSeg * 8);          \
        avl = *(const uint4*)(g_Wlo16 + aRow * NC + (kc) * 16 + aSeg * 8);          \
        bf0 = *(const float4*)&featB[(size_t)((kc) * 16 + (tid >> 5)) * NHW + (tid & 31) * 4];            \
        bf1 = *(const float4*)&featB[(size_t)((kc) * 16 + ((tid + 256) >> 5)) * NHW + (tid & 31) * 4];    \
    } while (0)

#define STORE_CHUNK(buf)                                                            \
    do {                                                                            \
        *(uint4*)(sAh + (buf) * 3072 + aRow * APITCH + aSeg * 8) = avh;             \
        *(uint4*)(sAl + (buf) * 3072 + aRow * APITCH + aSeg * 8) = avl;             \
        float4 xs[2] = {bf0, bf1};                                                  \
        _Pragma("unroll")                                                           \
        for (int ii = 0; ii < 2; ii++) {                                            \
            int idx = tid + ii * 256;                                               \
            int kk = idx >> 5, p4 = idx & 31;                                       \
            float4 x = xs[ii];                                                      \
            __half hx = __float2half_rn(x.x), hy = __float2half_rn(x.y);            \
            __half hz = __float2half_rn(x.z), hw = __float2half_rn(x.w);            \
            __half lx = __float2half_rn(x.x - __half2float(hx));                    \
            __half ly = __float2half_rn(x.y - __half2float(hy));                    \
            __half lz = __float2half_rn(x.z - __half2float(hz));                    \
            __half lw = __float2half_rn(x.w - __half2float(hw));                    \
            __half* dh = sBh + (buf) * 2176 + kk * BPITCH + p4 * 4;                 \
            __half* dl = sBl + (buf) * 2176 + kk * BPITCH + p4 * 4;                 \
            *(__half2*)(dh)     = __halves2half2(hx, hy);                           \
            *(__half2*)(dh + 2) = __halves2half2(hz, hw);                           \
            *(__half2*)(dl)     = __halves2half2(lx, ly);                           \
            *(__half2*)(dl + 2) = __halves2half2(lz, lw);                           \
        }                                                                           \
    } while (0)

    LOAD_CHUNK(0);
    STORE_CHUNK(0);
    __syncthreads();

    for (int kc = 0; kc < 8; kc++) {
        const int buf = kc & 1;
        if (kc < 7) LOAD_CHUNK(kc + 1);

        unsigned ah[4][4], al[4][4], bh[2][4], bl[2][4];
#pragma unroll
        for (int mt = 0; mt < 4; mt++) {
            int m0 = wm * 64 + mt * 16;
            unsigned adr = sptr(sAh + buf * 3072 + (m0 + aR) * APITCH + aC);
            ldsm4(ah[mt][0], ah[mt][1], ah[mt][2], ah[mt][3], adr);
            unsigned adl = sptr(sAl + buf * 3072 + (m0 + aR) * APITCH + aC);
            ldsm4(al[mt][0], al[mt][1], al[mt][2], al[mt][3], adl);
        }
#pragma unroll
        for (int j = 0; j < 2; j++) {
            int n0 = wn * 32 + j * 16;
            unsigned adr = sptr(sBh + buf * 2176 + bK * BPITCH + n0 + bC);
            ldsm4t(bh[j][0], bh[j][1], bh[j][2], bh[j][3], adr);
            unsigned adl = sptr(sBl + buf * 2176 + bK * BPITCH + n0 + bC);
            ldsm4t(bl[j][0], bl[j][1], bl[j][2], bl[j][3], adl);
        }

#pragma unroll
        for (int mt = 0; mt < 4; mt++)
#pragma unroll
            for (int nt = 0; nt < 4; nt++) {
                int j = nt >> 1, s2 = (nt & 1) * 2;
                unsigned bhv[2] = {bh[j][s2], bh[j][s2 + 1]};
                unsigned blv[2] = {bl[j][s2], bl[j][s2 + 1]};
                mma16816(acc[mt][nt], ah[mt], bhv);
                mma16816(acc[mt][nt], al[mt], bhv);
                mma16816(acc[mt][nt], ah[mt], blv);
            }

        if (kc < 7) STORE_CHUNK(buf ^ 1);
        __syncthreads();
    }

    // ---- epilogue: smem transpose, fold BN/relu/mask, coalesced writes ------
    float* S = (float*)smraw;   // [128][66]
    const float* maskB = g_maskF + (size_t)b * NHW;
    const float* cartB = cart + (size_t)b * 3 * NHW;

    for (int hf = 0; hf < 2; hf++) {
        __syncthreads();
        if ((wn >> 1) == hf) {
#pragma unroll
            for (int mt = 0; mt < 4; mt++) {
                int r0 = wm * 64 + mt * 16 + g;
#pragma unroll
                for (int nt = 0; nt < 4; nt++) {
                    int col = (wn & 1) * 32 + nt * 8 + 2 * tg;
                    S[r0 * SPITCH + col]     = acc[mt][nt][0];
                    S[r0 * SPITCH + col + 1] = acc[mt][nt][1];
                    S[(r0 + 8) * SPITCH + col]     = acc[mt][nt][2];
                    S[(r0 + 8) * SPITCH + col + 1] = acc[mt][nt][3];
                }
            }
        }
        __syncthreads();
#pragma unroll
        for (int i = 0; i < 8; i++) {
            int item = tid + i * 256;
            int px = item & 63, og = item >> 6;
            int p = ptile + hf * 64 + px;
            int o = og * 4;
            float t0 = fmaxf(S[(o + 0) * SPITCH + px] + g_fshift[o + 0], 0.f);
            float t1 = fmaxf(S[(o + 1) * SPITCH + px] + g_fshift[o + 1], 0.f);
            float t2 = fmaxf(S[(o + 2) * SPITCH + px] + g_fshift[o + 2], 0.f);
            float t3 = fmaxf(S[(o + 3) * SPITCH + px] + g_fshift[o + 3], 0.f);
            float c0 = cartB[p], c1 = cartB[NHW + p], c2 = cartB[2 * NHW + p];
            float qx = g_pws[(o + 0) * 3] * c0 + g_pws[(o + 0) * 3 + 1] * c1 + g_pws[(o + 0) * 3 + 2] * c2;
            float qy = g_pws[(o + 1) * 3] * c0 + g_pws[(o + 1) * 3 + 1] * c1 + g_pws[(o + 1) * 3 + 2] * c2;
            float qz = g_pws[(o + 2) * 3] * c0 + g_pws[(o + 2) * 3 + 1] * c1 + g_pws[(o + 2) * 3 + 2] * c2;
            float qw = g_pws[(o + 3) * 3] * c0 + g_pws[(o + 3) * 3 + 1] * c1 + g_pws[(o + 3) * 3 + 2] * c2;
            bool valid = (maskB[p] != 0.0f);
            float4 A4, B4;
            A4.x = valid ? t0 + qx + g_pshift[o + 0] : NEGF;
            A4.y = valid ? t1 + qy + g_pshift[o + 1] : NEGF;
            A4.z = valid ? t2 + qz + g_pshift[o + 2] : NEGF;
            A4.w = valid ? t3 + qw + g_pshift[o + 3] : NEGF;
            B4.x = valid ? t0 : NEGF;
            B4.y = valid ? t1 : NEGF;
            B4.z = valid ? t2 : NEGF;
            B4.w = valid ? t3 : NEGF;
            size_t base = ((size_t)b * 32 + og) * NHW + p;
            g_arrA[base] = A4;
            g_arrB[base] = B4;
        }
    }
}

// ---------------- pass 2: separable masked maxpool + fused e2c ---------------
#define HT 8

__device__ __forceinline__ float4 shfl_up4(float4 v) {
    float4 r;
    r.x = __shfl_up_sync(0xffffffffu, v.x, 1);
    r.y = __shfl_up_sync(0xffffffffu, v.y, 1);
    r.z = __shfl_up_sync(0xffffffffu, v.z, 1);
    r.w = __shfl_up_sync(0xffffffffu, v.w, 1);
    return r;
}
__device__ __forceinline__ float4 shfl_dn4(float4 v) {
    float4 r;
    r.x = __shfl_down_sync(0xffffffffu, v.x, 1);
    r.y = __shfl_down_sync(0xffffffffu, v.y, 1);
    r.z = __shfl_down_sync(0xffffffffu, v.z, 1);
    r.w = __shfl_down_sync(0xffffffffu, v.w, 1);
    return r;
}
__device__ __forceinline__ float4 max34(float4 a, float4 b, float4 c) {
    float4 r;
    r.x = fmaxf(fmaxf(a.x, b.x), c.x);
    r.y = fmaxf(fmaxf(a.y, b.y), c.y);
    r.z = fmaxf(fmaxf(a.z, b.z), c.z);
    r.w = fmaxf(fmaxf(a.w, b.w), c.w);
    return r;
}

__device__ __forceinline__ void hrow(int hh, int w, int lane,
                                     const float4* __restrict__ pA,
                                     const float4* __restrict__ pB,
                                     float4& ha, float4& hb) {
    const float4 NEG4 = make_float4(NEGF, NEGF, NEGF, NEGF);
    if ((unsigned)hh >= NH) { ha = NEG4; hb = NEG4; return; }
    int idx = hh * NW + w;
    float4 a = pA[idx];
    float4 al = shfl_up4(a);
    float4 ar = shfl_dn4(a);
    if (lane == 0)  al = (w > 0)      ? pA[idx - 1] : NEG4;
    if (lane == 31) ar = (w < NW - 1) ? pA[idx + 1] : NEG4;
    ha = max34(al, a, ar);
    float4 bb = pB[idx];
    float4 bl = shfl_up4(bb);
    float4 br = shfl_dn4(bb);
    if (lane == 0)  bl = (w > 0)      ? pB[idx - 1] : NEG4;
    if (lane == 31) br = (w < NW - 1) ? pB[idx + 1] : NEG4;
    hb = max34(bl, bb, br);
}

__global__ void __launch_bounds__(1024, 1)
pool_kernel(const float* __restrict__ cart, const float* __restrict__ ew,
            float* __restrict__ out) {
    __shared__ float red[3][32][32];
    const int b = blockIdx.z;
    const int h0 = blockIdx.y * HT;
    const int lane = threadIdx.x & 31, og = threadIdx.x >> 5;
    const int w = blockIdx.x * 32 + lane;
    const int o = og * 4;

    const size_t plane = ((size_t)b * 32 + og) * NHW;
    const float4* pA = g_arrA + plane;
    const float4* pB = g_arrB + plane;
    float* outB = out + ((size_t)b * NC + o) * NHW;
    const float* cartB = cart + (size_t)b * 3 * NHW;
    const float* mF = g_maskF + (size_t)b * NHW;

    float pw0[4], pw1[4], pw2[4], e0[4], e1[4], e2[4];
#pragma unroll
    for (int j = 0; j < 4; j++) {
        pw0[j] = g_pws[(o + j) * 3 + 0];
        pw1[j] = g_pws[(o + j) * 3 + 1];
        pw2[j] = g_pws[(o + j) * 3 + 2];
        e0[j] = ew[0 * NC + o + j];
        e1[j] = ew[1 * NC + o + j];
        e2[j] = ew[2 * NC + o + j];
    }

    float4 mA, mB, cA, cB, nA, nB;
    hrow(h0 - 1, w, lane, pA, pB, mA, mB);
    hrow(h0,     w, lane, pA, pB, cA, cB);

    for (int r = 0; r < HT; r++) {
        int h = h0 + r;
        hrow(h + 1, w, lane, pA, pB, nA, nB);
        int p = h * NW + w;
        float c0 = cartB[p], c1 = cartB[NHW + p], c2 = cartB[2 * NHW + p];
        float qx = pw0[0] * c0 + pw1[0] * c1 + pw2[0] * c2;
        float qy = pw0[1] * c0 + pw1[1] * c1 + pw2[1] * c2;
        float qz = pw0[2] * c0 + pw1[2] * c1 + pw2[2] * c2;
        float qw = pw0[3] * c0 + pw1[3] * c1 + pw2[3] * c2;

        float gx = fmaxf(fmaxf(fmaxf(fmaxf(mA.x, cA.x), nA.x) - qx,
                               fmaxf(fmaxf(mB.x, cB.x), nB.x)), 0.f);
        float gy = fmaxf(fmaxf(fmaxf(fmaxf(mA.y, cA.y), nA.y) - qy,
                               fmaxf(fmaxf(mB.y, cB.y), nB.y)), 0.f);
        float gz = fmaxf(fmaxf(fmaxf(fmaxf(mA.z, cA.z), nA.z) - qz,
                               fmaxf(fmaxf(mB.z, cB.z), nB.z)), 0.f);
        float gw = fmaxf(fmaxf(fmaxf(fmaxf(mA.w, cA.w), nA.w) - qw,
                               fmaxf(fmaxf(mB.w, cB.w), nB.w)), 0.f);

        outB[p] = gx;
        outB[NHW + p] = gy;
        outB[2 * NHW + p] = gz;
        outB[3 * NHW + p] = gw;

        red[0][og][lane] = e0[0] * gx + e0[1] * gy + e0[2] * gz + e0[3] * gw;
        red[1][og][lane] = e1[0] * gx + e1[1] * gy + e1[2] * gz + e1[3] * gw;
        red[2][og][lane] = e2[0] * gx + e2[1] * gy + e2[2] * gz + e2[3] * gw;
        __syncthreads();

        if (og < 3) {
            float s = 0.f;
#pragma unroll
            for (int u = 0; u < 32; u++) s += red[og][u][lane];
            float e2c = g_escale[og] * s + g_eshift[og];
            float m = mF[p];
            out[(size_t)NB * NC * NHW + ((size_t)b * 3 + og) * NHW + p] =
                cartB[og * NHW + p] + e2c * m;
        }
        __syncthreads();

        mA = cA; cA = nA;
        mB = cB; cB = nB;
    }
}

// ---------------- launch -----------------------------------------------------
extern "C" void kernel_launch(void* const* d_in, const int* in_sizes, int n_in,
                              void* d_out, int out_size) {
    const float* feat = (const float*)d_in[0];
    const float* cart = (const float*)d_in[1];
    const void*  mask = d_in[2];
    const float* pw = (const float*)d_in[3];
    const float* pg = (const float*)d_in[4];
    const float* pb = (const float*)d_in[5];
    const float* pm = (const float*)d_in[6];
    const float* pv = (const float*)d_in[7];
    const float* fw = (const float*)d_in[8];
    const float* fg = (const float*)d_in[9];
    const float* fbp = (const float*)d_in[10];
    const float* fm = (const float*)d_in[11];
    const float* fv = (const float*)d_in[12];
    const float* ew = (const float*)d_in[13];
    const float* eg = (const float*)d_in[14];
    const float* eb = (const float*)d_in[15];
    const float* em = (const float*)d_in[16];
    const float* ev = (const float*)d_in[17];

    detect_mask_kernel<<<1, 256>>>((const unsigned int*)mask);
    convert_mask_kernel<<<(NB * NHW + 255) / 256, 256>>>(mask);
    prep_kernel<<<64, 256>>>(fw, fg, fbp, fm, fv, pw, pg, pb, pm, pv, eg, eb, em, ev);

    dim3 g1(NHW / 128, NB);
    gemm_kernel<<<g1, 256>>>(feat, cart);

    dim3 g2(NW / 32, NH / HT, NB);
    pool_kernel<<<g2, 1024>>>(cart, ew, (float*)d_out);
}